// round 1
// baseline (speedup 1.0000x reference)
#include <cuda_runtime.h>
#include <math.h>

#define NTOK 1024
#define CQ   768
#define CZ   128
#define NH   16
#define HD   48

// ---------------- scratch (static device memory; no allocations) ----------------
__device__ float g_an  [NTOK * CQ];
__device__ float g_q   [NTOK * CQ];
__device__ float g_k   [NTOK * CQ];
__device__ float g_v   [NTOK * CQ];
__device__ float g_gate[NTOK * CQ];
__device__ float g_og  [NTOK * CQ];
__device__ float g_sc  [(size_t)NTOK * NH * NTOK];   // scores / probs, layout [i][h][j]

// ---------------- LayerNorm over token embedding a: [1024, 768] ----------------
__global__ void __launch_bounds__(256) ln_a_kernel(const float* __restrict__ a,
                                                   const float* __restrict__ gw,
                                                   const float* __restrict__ bw) {
    int row = blockIdx.x;
    int tid = threadIdx.x;
    const float* x = a + (size_t)row * CQ;
    __shared__ float red[256];

    float xv[3];
    float s = 0.f;
#pragma unroll
    for (int k = 0; k < 3; k++) { xv[k] = x[tid + k * 256]; s += xv[k]; }
    red[tid] = s; __syncthreads();
    for (int st = 128; st > 0; st >>= 1) { if (tid < st) red[tid] += red[tid + st]; __syncthreads(); }
    float mu = red[0] * (1.f / CQ);
    __syncthreads();

    float s2 = 0.f;
#pragma unroll
    for (int k = 0; k < 3; k++) { float d = xv[k] - mu; s2 += d * d; }
    red[tid] = s2; __syncthreads();
    for (int st = 128; st > 0; st >>= 1) { if (tid < st) red[tid] += red[tid + st]; __syncthreads(); }
    float rs = rsqrtf(red[0] * (1.f / CQ) + 1e-5f);

#pragma unroll
    for (int k = 0; k < 3; k++) {
        int i = tid + k * 256;
        g_an[(size_t)row * CQ + i] = (xv[k] - mu) * rs * gw[i] + bw[i];
    }
}

// ------- fused: LayerNorm(z) -> pair bias (zn @ w_z) + mask bias -> g_sc -------
// one block per i; warp per (i, j); 32 j's per iteration, 32 iterations.
__global__ void __launch_bounds__(1024) pair_bias_kernel(const float* __restrict__ z,
                                                         const float* __restrict__ mask,
                                                         const float* __restrict__ gz,
                                                         const float* __restrict__ bz,
                                                         const float* __restrict__ wz) {
    int i = blockIdx.x;
    int tid = threadIdx.x, warp = tid >> 5, lane = tid & 31;

    __shared__ __align__(16) float wzs[NH][CZ];     // transposed: [h][c]
    __shared__ __align__(16) float gzs[CZ], bzs[CZ];
    __shared__ float bias_s[NH][33];

    for (int t = tid; t < CZ * NH; t += 1024) {
        int c = t >> 4, h = t & 15;
        wzs[h][c] = wz[t];                          // wz layout [c][h]
    }
    if (tid < CZ) { gzs[tid] = gz[tid]; bzs[tid] = bz[tid]; }
    __syncthreads();

    float mi = mask[i];
    int c0 = lane * 4;

    for (int it = 0; it < 32; it++) {
        int j = it * 32 + warp;
        const float4 zr = *(const float4*)&z[((size_t)i * NTOK + j) * CZ + c0];

        float s = zr.x + zr.y + zr.z + zr.w;
#pragma unroll
        for (int o = 16; o > 0; o >>= 1) s += __shfl_xor_sync(0xffffffffu, s, o);
        float mu = s * (1.f / CZ);

        float d0 = zr.x - mu, d1 = zr.y - mu, d2 = zr.z - mu, d3 = zr.w - mu;
        float s2 = d0 * d0 + d1 * d1 + d2 * d2 + d3 * d3;
#pragma unroll
        for (int o = 16; o > 0; o >>= 1) s2 += __shfl_xor_sync(0xffffffffu, s2, o);
        float rs = rsqrtf(s2 * (1.f / CZ) + 1e-5f);

        float4 gv = *(const float4*)&gzs[c0];
        float4 bv = *(const float4*)&bzs[c0];
        float zn0 = d0 * rs * gv.x + bv.x;
        float zn1 = d1 * rs * gv.y + bv.y;
        float zn2 = d2 * rs * gv.z + bv.z;
        float zn3 = d3 * rs * gv.w + bv.w;

        float acc[NH];
#pragma unroll
        for (int h = 0; h < NH; h++) {
            float4 w4 = *(const float4*)&wzs[h][c0];
            acc[h] = zn0 * w4.x + zn1 * w4.y + zn2 * w4.z + zn3 * w4.w;
        }
#pragma unroll
        for (int h = 0; h < NH; h++) {
            float v = acc[h];
#pragma unroll
            for (int o = 16; o > 0; o >>= 1) v += __shfl_xor_sync(0xffffffffu, v, o);
            if (lane == 0) bias_s[h][warp] = v;
        }
        __syncthreads();
        if (tid < 512) {
            int h = tid >> 5, jj = tid & 31, jg = it * 32 + jj;
            float mb = 1.0e9f * (mi * mask[jg] - 1.f);
            g_sc[((size_t)i * NH + h) * NTOK + jg] = bias_s[h][jj] + mb;
        }
        __syncthreads();
    }
}

// ---------------- generic tiled fp32 GEMM: C = epi(A @ B)  (row-major) ----------------
// BM=BN=64, BK=16, 256 threads, 4x4 per thread, float4 smem traffic.
// EPI: 0=none, 1=scale, 2=sigmoid(x + bias[col]), 3=x + bias[col]
template <int EPI>
__global__ void __launch_bounds__(256) gemm_nn(const float* __restrict__ A,
                                               const float* __restrict__ B,
                                               float* __restrict__ C,
                                               int M, int Nn, int K,
                                               int lda, int ldb, int ldc,
                                               const float* __restrict__ bias,
                                               float scale) {
    __shared__ __align__(16) float As[16][64];
    __shared__ __align__(16) float Bs[16][64];
    int tid = threadIdx.x, tx = tid & 15, ty = tid >> 4;
    int m0 = blockIdx.y * 64, n0 = blockIdx.x * 64;

    float acc[4][4] = {};
    for (int k0 = 0; k0 < K; k0 += 16) {
        {
            int m = tid >> 2, kq = (tid & 3) * 4;
            float4 ra = *(const float4*)&A[(size_t)(m0 + m) * lda + k0 + kq];
            As[kq + 0][m] = ra.x; As[kq + 1][m] = ra.y;
            As[kq + 2][m] = ra.z; As[kq + 3][m] = ra.w;
        }
        {
            int kk = tid >> 4, nq = (tid & 15) * 4;
            *(float4*)&Bs[kk][nq] = *(const float4*)&B[(size_t)(k0 + kk) * ldb + n0 + nq];
        }
        __syncthreads();
#pragma unroll
        for (int kk = 0; kk < 16; kk++) {
            float4 a4 = *(const float4*)&As[kk][ty * 4];
            float4 b4 = *(const float4*)&Bs[kk][tx * 4];
            float av[4] = {a4.x, a4.y, a4.z, a4.w};
            float bv[4] = {b4.x, b4.y, b4.z, b4.w};
#pragma unroll
            for (int ii = 0; ii < 4; ii++)
#pragma unroll
                for (int jj = 0; jj < 4; jj++) acc[ii][jj] += av[ii] * bv[jj];
        }
        __syncthreads();
    }
#pragma unroll
    for (int ii = 0; ii < 4; ii++)
#pragma unroll
        for (int jj = 0; jj < 4; jj++) {
            int r = m0 + ty * 4 + ii, c = n0 + tx * 4 + jj;
            float v = acc[ii][jj];
            if (EPI == 1) v *= scale;
            if (EPI == 2) v = 1.f / (1.f + expf(-(v + bias[c])));
            if (EPI == 3) v += bias[c];
            C[(size_t)r * ldc + c] = v;
        }
}

// ---------------- scores += Q_h @ K_h^T  (adds into pair+mask bias) ----------------
__global__ void __launch_bounds__(256) scores_kernel() {
    int h = blockIdx.z;
    int i0 = blockIdx.y * 64, j0 = blockIdx.x * 64;
    __shared__ __align__(16) float QsT[HD][64];
    __shared__ __align__(16) float KsT[HD][64];
    int tid = threadIdx.x, tx = tid & 15, ty = tid >> 4;

    for (int e = tid; e < 64 * HD; e += 256) {
        int m = e / HD, d = e % HD;
        QsT[d][m] = g_q[(size_t)(i0 + m) * CQ + h * HD + d];
        KsT[d][m] = g_k[(size_t)(j0 + m) * CQ + h * HD + d];
    }
    __syncthreads();

    float acc[4][4] = {};
#pragma unroll 8
    for (int d = 0; d < HD; d++) {
        float4 a4 = *(const float4*)&QsT[d][ty * 4];
        float4 b4 = *(const float4*)&KsT[d][tx * 4];
        float av[4] = {a4.x, a4.y, a4.z, a4.w};
        float bv[4] = {b4.x, b4.y, b4.z, b4.w};
#pragma unroll
        for (int ii = 0; ii < 4; ii++)
#pragma unroll
            for (int jj = 0; jj < 4; jj++) acc[ii][jj] += av[ii] * bv[jj];
    }
#pragma unroll
    for (int ii = 0; ii < 4; ii++)
#pragma unroll
        for (int jj = 0; jj < 4; jj++) {
            size_t idx = ((size_t)(i0 + ty * 4 + ii) * NH + h) * NTOK + j0 + tx * 4 + jj;
            g_sc[idx] += acc[ii][jj];
        }
}

// ---------------- softmax over j for each (i, h) row of 1024 ----------------
__global__ void __launch_bounds__(256) softmax_kernel() {
    size_t row = blockIdx.x;
    float* p = g_sc + row * NTOK;
    int tid = threadIdx.x;
    __shared__ float red[256];

    float4 v = ((float4*)p)[tid];
    float m = fmaxf(fmaxf(v.x, v.y), fmaxf(v.z, v.w));
    red[tid] = m; __syncthreads();
    for (int s = 128; s > 0; s >>= 1) { if (tid < s) red[tid] = fmaxf(red[tid], red[tid + s]); __syncthreads(); }
    float M = red[0]; __syncthreads();

    v.x = expf(v.x - M); v.y = expf(v.y - M); v.z = expf(v.z - M); v.w = expf(v.w - M);
    float s4 = v.x + v.y + v.z + v.w;
    red[tid] = s4; __syncthreads();
    for (int s = 128; s > 0; s >>= 1) { if (tid < s) red[tid] += red[tid + s]; __syncthreads(); }
    float inv = 1.f / red[0];
    v.x *= inv; v.y *= inv; v.z *= inv; v.w *= inv;
    ((float4*)p)[tid] = v;
}

// ---------------- o = P @ V_h, gated by sigmoid gate (already applied) ----------------
__global__ void __launch_bounds__(256) pv_kernel() {
    int h = blockIdx.y;
    int i0 = blockIdx.x * 64;
    __shared__ __align__(16) float PsT[32][64];
    __shared__ float Vs[32][48];
    int tid = threadIdx.x, tx = tid & 15, ty = tid >> 4;

    float acc[4][3] = {};
    for (int k0 = 0; k0 < NTOK; k0 += 32) {
        for (int e = tid; e < 64 * 32; e += 256) {
            int m = e >> 5, kk = e & 31;
            PsT[kk][m] = g_sc[((size_t)(i0 + m) * NH + h) * NTOK + k0 + kk];
        }
        for (int e = tid; e < 32 * 48; e += 256) {
            int kk = e / 48, n = e % 48;
            Vs[kk][n] = g_v[(size_t)(k0 + kk) * CQ + h * HD + n];
        }
        __syncthreads();
#pragma unroll 8
        for (int kk = 0; kk < 32; kk++) {
            float4 a4 = *(const float4*)&PsT[kk][ty * 4];
            float av[4] = {a4.x, a4.y, a4.z, a4.w};
            float b0 = Vs[kk][tx * 3 + 0];
            float b1 = Vs[kk][tx * 3 + 1];
            float b2 = Vs[kk][tx * 3 + 2];
#pragma unroll
            for (int ii = 0; ii < 4; ii++) {
                acc[ii][0] += av[ii] * b0;
                acc[ii][1] += av[ii] * b1;
                acc[ii][2] += av[ii] * b2;
            }
        }
        __syncthreads();
    }
#pragma unroll
    for (int ii = 0; ii < 4; ii++)
#pragma unroll
        for (int jj = 0; jj < 3; jj++) {
            int r = i0 + ty * 4 + ii, c = h * HD + tx * 3 + jj;
            size_t idx = (size_t)r * CQ + c;
            g_og[idx] = acc[ii][jj] * g_gate[idx];
        }
}

// ------------------------------- launch -------------------------------
extern "C" void kernel_launch(void* const* d_in, const int* in_sizes, int n_in,
                              void* d_out, int out_size) {
    const float* a    = (const float*)d_in[0];
    const float* z    = (const float*)d_in[1];
    const float* mask = (const float*)d_in[2];
    const float* ga   = (const float*)d_in[3];
    const float* ba   = (const float*)d_in[4];
    const float* gz   = (const float*)d_in[5];
    const float* bz   = (const float*)d_in[6];
    const float* wz   = (const float*)d_in[7];
    const float* wq   = (const float*)d_in[8];
    const float* wk   = (const float*)d_in[9];
    const float* wv   = (const float*)d_in[10];
    const float* wg   = (const float*)d_in[11];
    const float* bg   = (const float*)d_in[12];
    const float* wo   = (const float*)d_in[13];
    const float* bo   = (const float*)d_in[14];
    float* out = (float*)d_out;

    float *p_an, *p_q, *p_k, *p_v, *p_gate, *p_og;
    cudaGetSymbolAddress((void**)&p_an,   g_an);
    cudaGetSymbolAddress((void**)&p_q,    g_q);
    cudaGetSymbolAddress((void**)&p_k,    g_k);
    cudaGetSymbolAddress((void**)&p_v,    g_v);
    cudaGetSymbolAddress((void**)&p_gate, g_gate);
    cudaGetSymbolAddress((void**)&p_og,   g_og);

    ln_a_kernel<<<NTOK, 256>>>(a, ga, ba);
    pair_bias_kernel<<<NTOK, 1024>>>(z, mask, gz, bz, wz);

    dim3 gqk(CQ / 64, NTOK / 64);
    float qscale = 1.0f / sqrtf((float)HD);
    gemm_nn<1><<<gqk, 256>>>(p_an, wq, p_q,    NTOK, CQ, CQ, CQ, CQ, CQ, nullptr, qscale);
    gemm_nn<0><<<gqk, 256>>>(p_an, wk, p_k,    NTOK, CQ, CQ, CQ, CQ, CQ, nullptr, 1.f);
    gemm_nn<0><<<gqk, 256>>>(p_an, wv, p_v,    NTOK, CQ, CQ, CQ, CQ, CQ, nullptr, 1.f);
    gemm_nn<2><<<gqk, 256>>>(p_an, wg, p_gate, NTOK, CQ, CQ, CQ, CQ, CQ, bg,      1.f);

    scores_kernel<<<dim3(NTOK / 64, NTOK / 64, NH), 256>>>();
    softmax_kernel<<<NTOK * NH, 256>>>();
    pv_kernel<<<dim3(NTOK / 64, NH), 256>>>();

    gemm_nn<3><<<gqk, 256>>>(p_og, wo, out, NTOK, CQ, CQ, CQ, CQ, CQ, bo, 1.f);
}

// round 2
// speedup vs baseline: 1.7409x; 1.7409x over previous
#include <cuda_runtime.h>
#include <math.h>

#define NTOK 1024
#define CQ   768
#define CZ   128
#define NH   16
#define HD   48

// ---------------- scratch (static device memory) ----------------
__device__ float g_an  [NTOK * CQ];
__device__ float g_q   [NTOK * CQ];
__device__ float g_k   [NTOK * CQ];
__device__ float g_v   [NTOK * CQ];
__device__ float g_gate[NTOK * CQ];
__device__ float g_og  [NTOK * CQ];
__device__ float g_sc  [(size_t)NTOK * NH * NTOK];   // pair+mask bias, layout [i][h][j]
__device__ float g_wp  [CZ * NH];                    // gz[c] * wz[c][h]
__device__ float g_Wh  [NH];                         // sum_c wp[c][h]
__device__ float g_ch  [NH];                         // sum_c bz[c] * wz[c][h]

// ---------------- LayerNorm of a: [1024, 768] ----------------
__global__ void __launch_bounds__(256) ln_a_kernel(const float* __restrict__ a,
                                                   const float* __restrict__ gw,
                                                   const float* __restrict__ bw) {
    int row = blockIdx.x;
    int tid = threadIdx.x;
    const float* x = a + (size_t)row * CQ;
    __shared__ float red[256];

    float xv[3];
    float s = 0.f;
#pragma unroll
    for (int k = 0; k < 3; k++) { xv[k] = x[tid + k * 256]; s += xv[k]; }
    red[tid] = s; __syncthreads();
    for (int st = 128; st > 0; st >>= 1) { if (tid < st) red[tid] += red[tid + st]; __syncthreads(); }
    float mu = red[0] * (1.f / CQ);
    __syncthreads();

    float s2 = 0.f;
#pragma unroll
    for (int k = 0; k < 3; k++) { float d = xv[k] - mu; s2 += d * d; }
    red[tid] = s2; __syncthreads();
    for (int st = 128; st > 0; st >>= 1) { if (tid < st) red[tid] += red[tid + st]; __syncthreads(); }
    float rs = rsqrtf(red[0] * (1.f / CQ) + 1e-5f);

#pragma unroll
    for (int k = 0; k < 3; k++) {
        int i = tid + k * 256;
        g_an[(size_t)row * CQ + i] = (xv[k] - mu) * rs * gw[i] + bw[i];
    }
}

// ---------------- tiny precompute for pair bias ----------------
__global__ void prep_kernel(const float* __restrict__ gz,
                            const float* __restrict__ bz,
                            const float* __restrict__ wz) {
    int tid = threadIdx.x;       // 128
    float gzc = gz[tid];
    for (int h = 0; h < NH; h++) g_wp[tid * NH + h] = gzc * wz[tid * NH + h];
    __syncthreads();
    if (tid < NH) {
        float W = 0.f, C = 0.f;
        for (int c = 0; c < CZ; c++) {
            W += g_wp[c * NH + tid];
            C += bz[c] * wz[c * NH + tid];
        }
        g_Wh[tid] = W;
        g_ch[tid] = C;
    }
}

// ---------------- pair bias: LN(z) @ w_z + mask, via algebraic form ----------------
// bias_h = rs*(dot(z, wp_h) - mu*W_h) + const_h
// block: 32 rows (fixed i, 32 consecutive j), 256 threads = 32 rows x 8 lanes (2 heads each)
__global__ void __launch_bounds__(256) pair_bias_kernel(const float* __restrict__ z,
                                                        const float* __restrict__ mask) {
    int b  = blockIdx.x;
    int i  = b >> 5;
    int j0 = (b & 31) * 32;
    int tid = threadIdx.x;
    int r = tid >> 3;           // 0..31 local row
    int q = tid & 7;            // lane within row group

    __shared__ float  zt[32][132];
    __shared__ float2 wp2[CZ][8];
    __shared__ float  sbias[NH][33];

    for (int t = tid; t < CZ * 8; t += 256) {
        int c = t >> 3, hh = t & 7;
        wp2[c][hh] = make_float2(g_wp[c * NH + 2 * hh], g_wp[c * NH + 2 * hh + 1]);
    }

    // load z row chunk (16 floats per thread) + stats
    const float* zrow = z + ((size_t)i * NTOK + j0 + r) * CZ;
    float s1 = 0.f, s2 = 0.f;
#pragma unroll
    for (int kk = 0; kk < 4; kk++) {
        int c4 = (q + 8 * kk) * 4;
        float4 v = *(const float4*)&zrow[c4];
        *(float4*)&zt[r][c4] = v;
        s1 += v.x + v.y + v.z + v.w;
        s2 += v.x * v.x + v.y * v.y + v.z * v.z + v.w * v.w;
    }
#pragma unroll
    for (int o = 4; o >= 1; o >>= 1) {
        s1 += __shfl_xor_sync(0xffffffffu, s1, o);
        s2 += __shfl_xor_sync(0xffffffffu, s2, o);
    }
    float mu = s1 * (1.f / CZ);
    float var = s2 * (1.f / CZ) - mu * mu;
    float rs = rsqrtf(var + 1e-5f);
    __syncthreads();

    // per-thread: full dot over c for 2 heads
    float a0 = 0.f, a1 = 0.f;
    const float* zr = zt[r];
#pragma unroll 8
    for (int c = 0; c < CZ; c += 4) {
        float4 zc = *(const float4*)&zr[c];
        float2 w0 = wp2[c + 0][q];
        float2 w1 = wp2[c + 1][q];
        float2 w2 = wp2[c + 2][q];
        float2 w3 = wp2[c + 3][q];
        a0 += zc.x * w0.x + zc.y * w1.x + zc.z * w2.x + zc.w * w3.x;
        a1 += zc.x * w0.y + zc.y * w1.y + zc.z * w2.y + zc.w * w3.y;
    }
    int h0 = 2 * q;
    sbias[h0    ][r] = rs * (a0 - mu * g_Wh[h0    ]) + g_ch[h0    ];
    sbias[h0 + 1][r] = rs * (a1 - mu * g_Wh[h0 + 1]) + g_ch[h0 + 1];
    __syncthreads();

    float mi = mask[i];
#pragma unroll
    for (int t = 0; t < 2; t++) {
        int v = tid + t * 256;
        int h = v >> 5, jj = v & 31;
        float mb = 1.0e9f * (mi * mask[j0 + jj] - 1.f);
        g_sc[((size_t)i * NH + h) * NTOK + j0 + jj] = sbias[h][jj] + mb;
    }
}

// ---------------- 128x64-tile fp32 GEMM core (M=1024, N=768, K=768 fixed strides) ----------------
// 256 threads, thread = 8x4 accumulators.
#define GEMM_BODY(Aptr, Bptr)                                                        \
    __shared__ float As[16][132];                                                    \
    __shared__ float Bs[16][64];                                                     \
    int tid = threadIdx.x;                                                           \
    int tx = tid & 15, ty = tid >> 4;                                                \
    int m0 = blockIdx.y * 128, n0 = blockIdx.x * 64;                                 \
    int lm = tid >> 1, lk = (tid & 1) * 8;                                           \
    int bk = tid >> 4, bn = (tid & 15) * 4;                                          \
    float acc[8][4] = {};                                                            \
    for (int k0 = 0; k0 < CQ; k0 += 16) {                                            \
        float4 a0 = *(const float4*)&Aptr[(size_t)(m0 + lm) * CQ + k0 + lk];         \
        float4 a1 = *(const float4*)&Aptr[(size_t)(m0 + lm) * CQ + k0 + lk + 4];     \
        As[lk + 0][lm] = a0.x; As[lk + 1][lm] = a0.y;                                \
        As[lk + 2][lm] = a0.z; As[lk + 3][lm] = a0.w;                                \
        As[lk + 4][lm] = a1.x; As[lk + 5][lm] = a1.y;                                \
        As[lk + 6][lm] = a1.z; As[lk + 7][lm] = a1.w;                                \
        *(float4*)&Bs[bk][bn] = *(const float4*)&Bptr[(size_t)(k0 + bk) * CQ + n0 + bn]; \
        __syncthreads();                                                             \
        _Pragma("unroll")                                                            \
        for (int kk = 0; kk < 16; kk++) {                                            \
            float4 av0 = *(const float4*)&As[kk][ty * 8];                            \
            float4 av1 = *(const float4*)&As[kk][ty * 8 + 4];                        \
            float4 bv  = *(const float4*)&Bs[kk][tx * 4];                            \
            float av[8] = {av0.x, av0.y, av0.z, av0.w, av1.x, av1.y, av1.z, av1.w};  \
            float bb[4] = {bv.x, bv.y, bv.z, bv.w};                                  \
            _Pragma("unroll")                                                        \
            for (int ii = 0; ii < 8; ii++)                                           \
                _Pragma("unroll")                                                    \
                for (int jj = 0; jj < 4; jj++) acc[ii][jj] += av[ii] * bb[jj];       \
        }                                                                            \
        __syncthreads();                                                             \
    }

// fused Q/K/V/Gate projections: blockIdx.z selects matrix + epilogue
__global__ void __launch_bounds__(256) qkvg_gemm(const float* __restrict__ A,
                                                 const float* __restrict__ wq,
                                                 const float* __restrict__ wk,
                                                 const float* __restrict__ wv,
                                                 const float* __restrict__ wg,
                                                 const float* __restrict__ bg,
                                                 float qscale) {
    int zi = blockIdx.z;
    const float* B = (zi == 0) ? wq : (zi == 1) ? wk : (zi == 2) ? wv : wg;
    float* O = (zi == 0) ? g_q : (zi == 1) ? g_k : (zi == 2) ? g_v : g_gate;
    GEMM_BODY(A, B)
#pragma unroll
    for (int ii = 0; ii < 8; ii++) {
        int row = m0 + ty * 8 + ii;
#pragma unroll
        for (int jj = 0; jj < 4; jj++) {
            int col = n0 + tx * 4 + jj;
            float v = acc[ii][jj];
            if (zi == 0) v *= qscale;
            if (zi == 3) v = 1.f / (1.f + __expf(-(v + bg[col])));
            O[(size_t)row * CQ + col] = v;
        }
    }
}

// out projection: C = A @ wo + bo
__global__ void __launch_bounds__(256) out_gemm(const float* __restrict__ A,
                                                const float* __restrict__ B,
                                                float* __restrict__ C,
                                                const float* __restrict__ bias) {
    GEMM_BODY(A, B)
#pragma unroll
    for (int ii = 0; ii < 8; ii++) {
        int row = m0 + ty * 8 + ii;
#pragma unroll
        for (int jj = 0; jj < 4; jj++) {
            int col = n0 + tx * 4 + jj;
            C[(size_t)row * CQ + col] = acc[ii][jj] + bias[col];
        }
    }
}

// ---------------- flash attention: per (i-tile 32, head). online softmax + PV + gating ----------------
__global__ void __launch_bounds__(256) flash_kernel() {
    int h  = blockIdx.y;
    int i0 = blockIdx.x * 32;
    int tid = threadIdx.x, tx = tid & 15, ty = tid >> 4;

    __shared__ float QsT[HD][33];
    __shared__ float KsT[HD][68];
    __shared__ float VsT[HD][68];
    __shared__ float Ps[32][68];

    // load Q tile, transposed
    for (int t = tid; t < 32 * 12; t += 256) {
        int rr = t / 12, dq = (t % 12) * 4;
        float4 qv = *(const float4*)&g_q[(size_t)(i0 + rr) * CQ + h * HD + dq];
        QsT[dq + 0][rr] = qv.x; QsT[dq + 1][rr] = qv.y;
        QsT[dq + 2][rr] = qv.z; QsT[dq + 3][rr] = qv.w;
    }

    int r0 = ty * 2, r1 = ty * 2 + 1;
    int d0 = tx * 3;
    float mrun0 = -1e30f, mrun1 = -1e30f;
    float l0 = 0.f, l1 = 0.f;
    float acc[2][3] = {};
    __syncthreads();

    for (int jt = 0; jt < 16; jt++) {
        int j0 = jt * 64;
        // load K, V tiles transposed
        for (int t = tid; t < 64 * 12; t += 256) {
            int jj = t / 12, dq = (t % 12) * 4;
            float4 kv = *(const float4*)&g_k[(size_t)(j0 + jj) * CQ + h * HD + dq];
            KsT[dq + 0][jj] = kv.x; KsT[dq + 1][jj] = kv.y;
            KsT[dq + 2][jj] = kv.z; KsT[dq + 3][jj] = kv.w;
            float4 vv = *(const float4*)&g_v[(size_t)(j0 + jj) * CQ + h * HD + dq];
            VsT[dq + 0][jj] = vv.x; VsT[dq + 1][jj] = vv.y;
            VsT[dq + 2][jj] = vv.z; VsT[dq + 3][jj] = vv.w;
        }
        __syncthreads();

        // S = bias + Q K^T
        float4 b0 = *(const float4*)&g_sc[((size_t)(i0 + r0) * NH + h) * NTOK + j0 + tx * 4];
        float4 b1 = *(const float4*)&g_sc[((size_t)(i0 + r1) * NH + h) * NTOK + j0 + tx * 4];
        float s0[4] = {b0.x, b0.y, b0.z, b0.w};
        float s1[4] = {b1.x, b1.y, b1.z, b1.w};
#pragma unroll 8
        for (int d = 0; d < HD; d++) {
            float q0 = QsT[d][r0], q1 = QsT[d][r1];
            float4 kv = *(const float4*)&KsT[d][tx * 4];
            s0[0] += q0 * kv.x; s0[1] += q0 * kv.y; s0[2] += q0 * kv.z; s0[3] += q0 * kv.w;
            s1[0] += q1 * kv.x; s1[1] += q1 * kv.y; s1[2] += q1 * kv.z; s1[3] += q1 * kv.w;
        }

        float mt0 = fmaxf(fmaxf(s0[0], s0[1]), fmaxf(s0[2], s0[3]));
        float mt1 = fmaxf(fmaxf(s1[0], s1[1]), fmaxf(s1[2], s1[3]));
#pragma unroll
        for (int o = 8; o >= 1; o >>= 1) {
            mt0 = fmaxf(mt0, __shfl_xor_sync(0xffffffffu, mt0, o));
            mt1 = fmaxf(mt1, __shfl_xor_sync(0xffffffffu, mt1, o));
        }
        float mn0 = fmaxf(mrun0, mt0), mn1 = fmaxf(mrun1, mt1);
        float al0 = __expf(mrun0 - mn0), al1 = __expf(mrun1 - mn1);
        mrun0 = mn0; mrun1 = mn1;
#pragma unroll
        for (int j = 0; j < 4; j++) { s0[j] = __expf(s0[j] - mn0); s1[j] = __expf(s1[j] - mn1); }
        float ps0 = s0[0] + s0[1] + s0[2] + s0[3];
        float ps1 = s1[0] + s1[1] + s1[2] + s1[3];
#pragma unroll
        for (int o = 8; o >= 1; o >>= 1) {
            ps0 += __shfl_xor_sync(0xffffffffu, ps0, o);
            ps1 += __shfl_xor_sync(0xffffffffu, ps1, o);
        }
        l0 = l0 * al0 + ps0;
        l1 = l1 * al1 + ps1;
#pragma unroll
        for (int j = 0; j < 3; j++) { acc[0][j] *= al0; acc[1][j] *= al1; }
        *(float4*)&Ps[r0][tx * 4] = make_float4(s0[0], s0[1], s0[2], s0[3]);
        *(float4*)&Ps[r1][tx * 4] = make_float4(s1[0], s1[1], s1[2], s1[3]);
        __syncthreads();

        // PV accumulate
#pragma unroll
        for (int kk = 0; kk < 64; kk += 4) {
            float4 p0 = *(const float4*)&Ps[r0][kk];
            float4 p1 = *(const float4*)&Ps[r1][kk];
#pragma unroll
            for (int j = 0; j < 3; j++) {
                float4 vv = *(const float4*)&VsT[d0 + j][kk];
                acc[0][j] += p0.x * vv.x + p0.y * vv.y + p0.z * vv.z + p0.w * vv.w;
                acc[1][j] += p1.x * vv.x + p1.y * vv.y + p1.z * vv.z + p1.w * vv.w;
            }
        }
        __syncthreads();
    }

    float inv0 = 1.f / l0, inv1 = 1.f / l1;
#pragma unroll
    for (int j = 0; j < 3; j++) {
        size_t i0x = (size_t)(i0 + r0) * CQ + h * HD + d0 + j;
        size_t i1x = (size_t)(i0 + r1) * CQ + h * HD + d0 + j;
        g_og[i0x] = acc[0][j] * inv0 * g_gate[i0x];
        g_og[i1x] = acc[1][j] * inv1 * g_gate[i1x];
    }
}

// ------------------------------- launch -------------------------------
extern "C" void kernel_launch(void* const* d_in, const int* in_sizes, int n_in,
                              void* d_out, int out_size) {
    const float* a    = (const float*)d_in[0];
    const float* z    = (const float*)d_in[1];
    const float* mask = (const float*)d_in[2];
    const float* ga   = (const float*)d_in[3];
    const float* ba   = (const float*)d_in[4];
    const float* gz   = (const float*)d_in[5];
    const float* bz   = (const float*)d_in[6];
    const float* wz   = (const float*)d_in[7];
    const float* wq   = (const float*)d_in[8];
    const float* wk   = (const float*)d_in[9];
    const float* wv   = (const float*)d_in[10];
    const float* wg   = (const float*)d_in[11];
    const float* bg   = (const float*)d_in[12];
    const float* wo   = (const float*)d_in[13];
    const float* bo   = (const float*)d_in[14];
    float* out = (float*)d_out;

    float *p_an, *p_og;
    cudaGetSymbolAddress((void**)&p_an, g_an);
    cudaGetSymbolAddress((void**)&p_og, g_og);

    ln_a_kernel<<<NTOK, 256>>>(a, ga, ba);
    prep_kernel<<<1, 128>>>(gz, bz, wz);
    pair_bias_kernel<<<NTOK * 32, 256>>>(z, mask);

    float qscale = 1.0f / sqrtf((float)HD);
    qkvg_gemm<<<dim3(CQ / 64, NTOK / 128, 4), 256>>>(p_an, wq, wk, wv, wg, bg, qscale);

    flash_kernel<<<dim3(NTOK / 32, NH), 256>>>();

    out_gemm<<<dim3(CQ / 64, NTOK / 128), 256>>>(p_og, wo, out, bo);
}

// round 3
// speedup vs baseline: 2.1161x; 1.2155x over previous
#include <cuda_runtime.h>
#include <math.h>

#define NTOK 1024
#define CQ   768
#define CZ   128
#define NH   16
#define HD   48

// ---------------- scratch (static device memory) ----------------
__device__ float g_an  [NTOK * CQ];
__device__ float g_q   [NTOK * CQ];
__device__ float g_k   [NTOK * CQ];
__device__ float g_v   [NTOK * CQ];
__device__ float g_gate[NTOK * CQ];
__device__ float g_og  [NTOK * CQ];
__device__ float g_sc  [(size_t)NTOK * NH * NTOK];   // pair+mask bias, layout [i][h][j]
__device__ float g_wp  [CZ * NH];
__device__ float g_Wh  [NH];
__device__ float g_ch  [NH];

// ---------------- tf32 helpers ----------------
__device__ __forceinline__ unsigned f2tf(float x) {
    unsigned u; asm("cvt.rna.tf32.f32 %0, %1;" : "=r"(u) : "f"(x)); return u;
}
__device__ __forceinline__ float tf32f(float x) { return __uint_as_float(f2tf(x)); }

#define MMA_TF32(c, a, b0_, b1_)                                              \
    asm volatile("mma.sync.aligned.m16n8k8.row.col.f32.tf32.tf32.f32 "        \
                 "{%0,%1,%2,%3}, {%4,%5,%6,%7}, {%8,%9}, {%0,%1,%2,%3};"      \
                 : "+f"(c[0]), "+f"(c[1]), "+f"(c[2]), "+f"(c[3])             \
                 : "r"(a[0]), "r"(a[1]), "r"(a[2]), "r"(a[3]),                \
                   "r"(b0_), "r"(b1_));

// ---------------- LayerNorm of a ----------------
__global__ void __launch_bounds__(256) ln_a_kernel(const float* __restrict__ a,
                                                   const float* __restrict__ gw,
                                                   const float* __restrict__ bw) {
    int row = blockIdx.x;
    int tid = threadIdx.x;
    const float* x = a + (size_t)row * CQ;
    __shared__ float red[256];

    float xv[3];
    float s = 0.f;
#pragma unroll
    for (int k = 0; k < 3; k++) { xv[k] = x[tid + k * 256]; s += xv[k]; }
    red[tid] = s; __syncthreads();
    for (int st = 128; st > 0; st >>= 1) { if (tid < st) red[tid] += red[tid + st]; __syncthreads(); }
    float mu = red[0] * (1.f / CQ);
    __syncthreads();

    float s2 = 0.f;
#pragma unroll
    for (int k = 0; k < 3; k++) { float d = xv[k] - mu; s2 += d * d; }
    red[tid] = s2; __syncthreads();
    for (int st = 128; st > 0; st >>= 1) { if (tid < st) red[tid] += red[tid + st]; __syncthreads(); }
    float rs = rsqrtf(red[0] * (1.f / CQ) + 1e-5f);

#pragma unroll
    for (int k = 0; k < 3; k++) {
        int i = tid + k * 256;
        g_an[(size_t)row * CQ + i] = (xv[k] - mu) * rs * gw[i] + bw[i];
    }
}

// ---------------- pair-bias precompute ----------------
__global__ void prep_kernel(const float* __restrict__ gz,
                            const float* __restrict__ bz,
                            const float* __restrict__ wz) {
    int tid = threadIdx.x;       // 128
    float gzc = gz[tid];
    for (int h = 0; h < NH; h++) g_wp[tid * NH + h] = gzc * wz[tid * NH + h];
    __syncthreads();
    if (tid < NH) {
        float W = 0.f, C = 0.f;
        for (int c = 0; c < CZ; c++) {
            W += g_wp[c * NH + tid];
            C += bz[c] * wz[c * NH + tid];
        }
        g_Wh[tid] = W;
        g_ch[tid] = C;
    }
}

// ---------------- pair bias: LN(z) @ w_z + mask -> g_sc ----------------
__global__ void __launch_bounds__(256) pair_bias_kernel(const float* __restrict__ z,
                                                        const float* __restrict__ mask) {
    int b  = blockIdx.x;
    int i  = b >> 5;
    int j0 = (b & 31) * 32;
    int tid = threadIdx.x;
    int r = tid >> 3;
    int q = tid & 7;

    __shared__ float  zt[32][132];
    __shared__ float2 wp2[CZ][8];
    __shared__ float  sbias[NH][33];

    for (int t = tid; t < CZ * 8; t += 256) {
        int c = t >> 3, hh = t & 7;
        wp2[c][hh] = make_float2(g_wp[c * NH + 2 * hh], g_wp[c * NH + 2 * hh + 1]);
    }

    const float* zrow = z + ((size_t)i * NTOK + j0 + r) * CZ;
    float s1 = 0.f, s2 = 0.f;
#pragma unroll
    for (int kk = 0; kk < 4; kk++) {
        int c4 = (q + 8 * kk) * 4;
        float4 v = *(const float4*)&zrow[c4];
        *(float4*)&zt[r][c4] = v;
        s1 += v.x + v.y + v.z + v.w;
        s2 += v.x * v.x + v.y * v.y + v.z * v.z + v.w * v.w;
    }
#pragma unroll
    for (int o = 4; o >= 1; o >>= 1) {
        s1 += __shfl_xor_sync(0xffffffffu, s1, o);
        s2 += __shfl_xor_sync(0xffffffffu, s2, o);
    }
    float mu = s1 * (1.f / CZ);
    float var = s2 * (1.f / CZ) - mu * mu;
    float rs = rsqrtf(var + 1e-5f);
    __syncthreads();

    float a0 = 0.f, a1 = 0.f;
    const float* zr = zt[r];
#pragma unroll 8
    for (int c = 0; c < CZ; c += 4) {
        float4 zc = *(const float4*)&zr[c];
        float2 w0 = wp2[c + 0][q];
        float2 w1 = wp2[c + 1][q];
        float2 w2 = wp2[c + 2][q];
        float2 w3 = wp2[c + 3][q];
        a0 += zc.x * w0.x + zc.y * w1.x + zc.z * w2.x + zc.w * w3.x;
        a1 += zc.x * w0.y + zc.y * w1.y + zc.z * w2.y + zc.w * w3.y;
    }
    int h0 = 2 * q;
    sbias[h0    ][r] = rs * (a0 - mu * g_Wh[h0    ]) + g_ch[h0    ];
    sbias[h0 + 1][r] = rs * (a1 - mu * g_Wh[h0 + 1]) + g_ch[h0 + 1];
    __syncthreads();

    float mi = mask[i];
#pragma unroll
    for (int t = 0; t < 2; t++) {
        int v = tid + t * 256;
        int h = v >> 5, jj = v & 31;
        float mb = 1.0e9f * (mi * mask[j0 + jj] - 1.f);
        g_sc[((size_t)i * NH + h) * NTOK + j0 + jj] = sbias[h][jj] + mb;
    }
}

// ================= 3xTF32 mma GEMM core: 128x64 tile, 256 thr =================
// sA: [32][136] (A transposed, k-major rows), sB: [32][72]
__device__ __forceinline__ void gemm_core(const float* __restrict__ A,
                                          const float* __restrict__ B,
                                          float c[2][4][4],
                                          float* sA, float* sB) {
    int tid  = threadIdx.x;
    int lane = tid & 31, w = tid >> 5;
    int wm = w & 3, wn = w >> 2;
    int g = lane >> 2, t = lane & 3;
    int m0 = blockIdx.y * 128, n0 = blockIdx.x * 64;
    int arow = tid >> 1, akq = (tid & 1) * 16;
    int bk = tid >> 3, bn = (tid & 7) * 8;

    for (int k0 = 0; k0 < CQ; k0 += 32) {
        __syncthreads();
#pragma unroll
        for (int i = 0; i < 4; i++) {
            float4 v = *(const float4*)&A[(size_t)(m0 + arow) * CQ + k0 + akq + i * 4];
            sA[(akq + i * 4 + 0) * 136 + arow] = v.x;
            sA[(akq + i * 4 + 1) * 136 + arow] = v.y;
            sA[(akq + i * 4 + 2) * 136 + arow] = v.z;
            sA[(akq + i * 4 + 3) * 136 + arow] = v.w;
        }
#pragma unroll
        for (int i = 0; i < 2; i++) {
            *(float4*)&sB[bk * 72 + bn + i * 4] =
                *(const float4*)&B[(size_t)(k0 + bk) * CQ + n0 + bn + i * 4];
        }
        __syncthreads();

#pragma unroll
        for (int ks = 0; ks < 4; ks++) {
            int kk = ks * 8;
            unsigned Ah[2][4], Al[2][4], Bh[4][2], Bl[4][2];
#pragma unroll
            for (int mt = 0; mt < 2; mt++) {
                int mb = wm * 32 + mt * 16 + g;
                float f0 = sA[(kk + t) * 136 + mb];
                float f1 = sA[(kk + t) * 136 + mb + 8];
                float f2 = sA[(kk + t + 4) * 136 + mb];
                float f3 = sA[(kk + t + 4) * 136 + mb + 8];
                float h0 = tf32f(f0), h1 = tf32f(f1), h2 = tf32f(f2), h3 = tf32f(f3);
                Ah[mt][0] = __float_as_uint(h0); Al[mt][0] = f2tf(f0 - h0);
                Ah[mt][1] = __float_as_uint(h1); Al[mt][1] = f2tf(f1 - h1);
                Ah[mt][2] = __float_as_uint(h2); Al[mt][2] = f2tf(f2 - h2);
                Ah[mt][3] = __float_as_uint(h3); Al[mt][3] = f2tf(f3 - h3);
            }
#pragma unroll
            for (int nt = 0; nt < 4; nt++) {
                int nb = wn * 32 + nt * 8 + g;
                float f0 = sB[(kk + t) * 72 + nb];
                float f1 = sB[(kk + t + 4) * 72 + nb];
                float h0 = tf32f(f0), h1 = tf32f(f1);
                Bh[nt][0] = __float_as_uint(h0); Bl[nt][0] = f2tf(f0 - h0);
                Bh[nt][1] = __float_as_uint(h1); Bl[nt][1] = f2tf(f1 - h1);
            }
#pragma unroll
            for (int mt = 0; mt < 2; mt++)
#pragma unroll
                for (int nt = 0; nt < 4; nt++) {
                    MMA_TF32(c[mt][nt], Ah[mt], Bh[nt][0], Bh[nt][1]);
                    MMA_TF32(c[mt][nt], Ah[mt], Bl[nt][0], Bl[nt][1]);
                    MMA_TF32(c[mt][nt], Al[mt], Bh[nt][0], Bh[nt][1]);
                }
        }
    }
}

// fused Q/K/V/Gate projections
__global__ void __launch_bounds__(256) qkvg_mma(const float* __restrict__ A,
                                                const float* __restrict__ wq,
                                                const float* __restrict__ wk,
                                                const float* __restrict__ wv,
                                                const float* __restrict__ wg,
                                                const float* __restrict__ bg,
                                                float qscale) {
    __shared__ float sA[32 * 136];
    __shared__ float sB[32 * 72];
    int zi = blockIdx.z;
    const float* B = (zi == 0) ? wq : (zi == 1) ? wk : (zi == 2) ? wv : wg;
    float* O = (zi == 0) ? g_q : (zi == 1) ? g_k : (zi == 2) ? g_v : g_gate;

    float c[2][4][4] = {};
    gemm_core(A, B, c, sA, sB);

    int lane = threadIdx.x & 31, w = threadIdx.x >> 5;
    int wm = w & 3, wn = w >> 2;
    int g = lane >> 2, t = lane & 3;
    int m0 = blockIdx.y * 128, n0 = blockIdx.x * 64;
#pragma unroll
    for (int mt = 0; mt < 2; mt++) {
        int r0 = m0 + wm * 32 + mt * 16 + g;
#pragma unroll
        for (int nt = 0; nt < 4; nt++) {
            int col = n0 + wn * 32 + nt * 8 + 2 * t;
            float v0 = c[mt][nt][0], v1 = c[mt][nt][1];
            float v2 = c[mt][nt][2], v3 = c[mt][nt][3];
            if (zi == 0) { v0 *= qscale; v1 *= qscale; v2 *= qscale; v3 *= qscale; }
            if (zi == 3) {
                float2 bb = *(const float2*)&bg[col];
                v0 = 1.f / (1.f + __expf(-(v0 + bb.x)));
                v1 = 1.f / (1.f + __expf(-(v1 + bb.y)));
                v2 = 1.f / (1.f + __expf(-(v2 + bb.x)));
                v3 = 1.f / (1.f + __expf(-(v3 + bb.y)));
            }
            *(float2*)&O[(size_t)r0 * CQ + col]       = make_float2(v0, v1);
            *(float2*)&O[(size_t)(r0 + 8) * CQ + col] = make_float2(v2, v3);
        }
    }
}

// out projection
__global__ void __launch_bounds__(256) out_mma(const float* __restrict__ A,
                                               const float* __restrict__ B,
                                               float* __restrict__ C,
                                               const float* __restrict__ bias) {
    __shared__ float sA[32 * 136];
    __shared__ float sB[32 * 72];
    float c[2][4][4] = {};
    gemm_core(A, B, c, sA, sB);

    int lane = threadIdx.x & 31, w = threadIdx.x >> 5;
    int wm = w & 3, wn = w >> 2;
    int g = lane >> 2, t = lane & 3;
    int m0 = blockIdx.y * 128, n0 = blockIdx.x * 64;
#pragma unroll
    for (int mt = 0; mt < 2; mt++) {
        int r0 = m0 + wm * 32 + mt * 16 + g;
#pragma unroll
        for (int nt = 0; nt < 4; nt++) {
            int col = n0 + wn * 32 + nt * 8 + 2 * t;
            float2 bb = *(const float2*)&bias[col];
            *(float2*)&C[(size_t)r0 * CQ + col] =
                make_float2(c[mt][nt][0] + bb.x, c[mt][nt][1] + bb.y);
            *(float2*)&C[(size_t)(r0 + 8) * CQ + col] =
                make_float2(c[mt][nt][2] + bb.x, c[mt][nt][3] + bb.y);
        }
    }
}

// ================= flash attention on mma: 64 rows x 1 head per block =================
// 128 threads = 4 warps, warp owns 16 rows. dyn smem: Ks[64][68] | Vs[64][72] | Ps[4][16][68]
__global__ void __launch_bounds__(128) flash_mma() {
    extern __shared__ float fsm[];
    float* Ks = fsm;                      // 64*68 = 4352
    float* Vs = fsm + 4352;               // 64*72 = 4608
    float* Ps = fsm + 4352 + 4608;        // 4*16*68 = 4352

    int h  = blockIdx.y;
    int i0 = blockIdx.x * 64;
    int tid = threadIdx.x, w = tid >> 5, lane = tid & 31;
    int g = lane >> 2, t = lane & 3;
    float* Pw = Ps + w * (16 * 68);
    int irow = i0 + w * 16 + g;

    // persistent Q fragments (tf32)
    unsigned aq[6][4];
    {
        const float* q0 = g_q + (size_t)irow * CQ + h * HD;
        const float* q8 = q0 + 8 * CQ;
#pragma unroll
        for (int ks = 0; ks < 6; ks++) {
            aq[ks][0] = f2tf(q0[ks * 8 + t]);
            aq[ks][1] = f2tf(q8[ks * 8 + t]);
            aq[ks][2] = f2tf(q0[ks * 8 + t + 4]);
            aq[ks][3] = f2tf(q8[ks * 8 + t + 4]);
        }
    }

    float o[6][4] = {};
    float mrunA = -1e30f, mrunB = -1e30f, lA = 0.f, lB = 0.f;

    for (int jt = 0; jt < 16; jt++) {
        int j0 = jt * 64;
        __syncthreads();
        // load K/V tiles (pre-rounded to tf32)
        for (int e = tid; e < 768; e += 128) {
            int r = e / 12, cc = (e % 12) * 4;
            float4 kv = *(const float4*)&g_k[(size_t)(j0 + r) * CQ + h * HD + cc];
            Ks[r * 68 + cc + 0] = tf32f(kv.x); Ks[r * 68 + cc + 1] = tf32f(kv.y);
            Ks[r * 68 + cc + 2] = tf32f(kv.z); Ks[r * 68 + cc + 3] = tf32f(kv.w);
            float4 vv = *(const float4*)&g_v[(size_t)(j0 + r) * CQ + h * HD + cc];
            Vs[r * 72 + cc + 0] = tf32f(vv.x); Vs[r * 72 + cc + 1] = tf32f(vv.y);
            Vs[r * 72 + cc + 2] = tf32f(vv.z); Vs[r * 72 + cc + 3] = tf32f(vv.w);
        }
        // stage this warp's bias tile (coalesced) into Pw
        for (int e = lane; e < 256; e += 32) {
            int r = e >> 4, c4 = (e & 15) * 4;
            *(float4*)&Pw[r * 68 + c4] =
                *(const float4*)&g_sc[((size_t)(i0 + w * 16 + r) * NH + h) * NTOK + j0 + c4];
        }
        __syncthreads();

        // S = bias + Q K^T
        float s[8][4];
#pragma unroll
        for (int nt = 0; nt < 8; nt++) {
            float2 bA = *(const float2*)&Pw[g * 68 + nt * 8 + 2 * t];
            float2 bB = *(const float2*)&Pw[(g + 8) * 68 + nt * 8 + 2 * t];
            s[nt][0] = bA.x; s[nt][1] = bA.y; s[nt][2] = bB.x; s[nt][3] = bB.y;
        }
#pragma unroll
        for (int ks = 0; ks < 6; ks++) {
#pragma unroll
            for (int nt = 0; nt < 8; nt++) {
                unsigned b0 = __float_as_uint(Ks[(nt * 8 + g) * 68 + ks * 8 + t]);
                unsigned b1 = __float_as_uint(Ks[(nt * 8 + g) * 68 + ks * 8 + t + 4]);
                MMA_TF32(s[nt], aq[ks], b0, b1);
            }
        }

        // online softmax (rows g and g+8)
        float mA = -1e30f, mB = -1e30f;
#pragma unroll
        for (int nt = 0; nt < 8; nt++) {
            mA = fmaxf(mA, fmaxf(s[nt][0], s[nt][1]));
            mB = fmaxf(mB, fmaxf(s[nt][2], s[nt][3]));
        }
#pragma unroll
        for (int oo = 1; oo <= 2; oo <<= 1) {
            mA = fmaxf(mA, __shfl_xor_sync(0xffffffffu, mA, oo));
            mB = fmaxf(mB, __shfl_xor_sync(0xffffffffu, mB, oo));
        }
        float mnA = fmaxf(mrunA, mA), mnB = fmaxf(mrunB, mB);
        float alA = __expf(mrunA - mnA), alB = __expf(mrunB - mnB);
        mrunA = mnA; mrunB = mnB;

        float sumA = 0.f, sumB = 0.f;
#pragma unroll
        for (int nt = 0; nt < 8; nt++) {
            s[nt][0] = __expf(s[nt][0] - mnA); s[nt][1] = __expf(s[nt][1] - mnA);
            s[nt][2] = __expf(s[nt][2] - mnB); s[nt][3] = __expf(s[nt][3] - mnB);
            sumA += s[nt][0] + s[nt][1];
            sumB += s[nt][2] + s[nt][3];
        }
#pragma unroll
        for (int oo = 1; oo <= 2; oo <<= 1) {
            sumA += __shfl_xor_sync(0xffffffffu, sumA, oo);
            sumB += __shfl_xor_sync(0xffffffffu, sumB, oo);
        }
        lA = lA * alA + sumA;
        lB = lB * alB + sumB;
#pragma unroll
        for (int nd = 0; nd < 6; nd++) {
            o[nd][0] *= alA; o[nd][1] *= alA;
            o[nd][2] *= alB; o[nd][3] *= alB;
        }

        // write P (tf32-rounded) into Pw
#pragma unroll
        for (int nt = 0; nt < 8; nt++) {
            *(float2*)&Pw[g * 68 + nt * 8 + 2 * t]       = make_float2(tf32f(s[nt][0]), tf32f(s[nt][1]));
            *(float2*)&Pw[(g + 8) * 68 + nt * 8 + 2 * t] = make_float2(tf32f(s[nt][2]), tf32f(s[nt][3]));
        }
        __syncwarp();

        // O += P V
#pragma unroll
        for (int ks = 0; ks < 8; ks++) {
            unsigned pa[4];
            pa[0] = __float_as_uint(Pw[g * 68 + ks * 8 + t]);
            pa[1] = __float_as_uint(Pw[(g + 8) * 68 + ks * 8 + t]);
            pa[2] = __float_as_uint(Pw[g * 68 + ks * 8 + t + 4]);
            pa[3] = __float_as_uint(Pw[(g + 8) * 68 + ks * 8 + t + 4]);
#pragma unroll
            for (int nd = 0; nd < 6; nd++) {
                unsigned b0 = __float_as_uint(Vs[(ks * 8 + t) * 72 + nd * 8 + g]);
                unsigned b1 = __float_as_uint(Vs[(ks * 8 + t + 4) * 72 + nd * 8 + g]);
                MMA_TF32(o[nd], pa, b0, b1);
            }
        }
    }

    // epilogue: normalize, gate, store
    float iA = 1.f / lA, iB = 1.f / lB;
#pragma unroll
    for (int nd = 0; nd < 6; nd++) {
        int col = h * HD + nd * 8 + 2 * t;
        size_t iAx = (size_t)irow * CQ + col;
        size_t iBx = (size_t)(irow + 8) * CQ + col;
        float2 ga = *(const float2*)&g_gate[iAx];
        float2 gb = *(const float2*)&g_gate[iBx];
        *(float2*)&g_og[iAx] = make_float2(o[nd][0] * iA * ga.x, o[nd][1] * iA * ga.y);
        *(float2*)&g_og[iBx] = make_float2(o[nd][2] * iB * gb.x, o[nd][3] * iB * gb.y);
    }
}

// ------------------------------- launch -------------------------------
extern "C" void kernel_launch(void* const* d_in, const int* in_sizes, int n_in,
                              void* d_out, int out_size) {
    const float* a    = (const float*)d_in[0];
    const float* z    = (const float*)d_in[1];
    const float* mask = (const float*)d_in[2];
    const float* ga   = (const float*)d_in[3];
    const float* ba   = (const float*)d_in[4];
    const float* gz   = (const float*)d_in[5];
    const float* bz   = (const float*)d_in[6];
    const float* wz   = (const float*)d_in[7];
    const float* wq   = (const float*)d_in[8];
    const float* wk   = (const float*)d_in[9];
    const float* wv   = (const float*)d_in[10];
    const float* wg   = (const float*)d_in[11];
    const float* bg   = (const float*)d_in[12];
    const float* wo   = (const float*)d_in[13];
    const float* bo   = (const float*)d_in[14];
    float* out = (float*)d_out;

    float *p_an, *p_og;
    cudaGetSymbolAddress((void**)&p_an, g_an);
    cudaGetSymbolAddress((void**)&p_og, g_og);

    static int smem_set = 0;
    if (!smem_set) {
        cudaFuncSetAttribute(flash_mma, cudaFuncAttributeMaxDynamicSharedMemorySize, 53248);
        smem_set = 1;
    }

    ln_a_kernel<<<NTOK, 256>>>(a, ga, ba);
    prep_kernel<<<1, 128>>>(gz, bz, wz);
    pair_bias_kernel<<<NTOK * 32, 256>>>(z, mask);

    float qscale = 1.0f / sqrtf((float)HD);
    qkvg_mma<<<dim3(CQ / 64, NTOK / 128, 4), 256>>>(p_an, wq, wk, wv, wg, bg, qscale);

    flash_mma<<<dim3(NTOK / 64, NH), 128, 53248>>>();

    out_mma<<<dim3(CQ / 64, NTOK / 128), 256>>>(p_og, wo, out, bo);
}

// round 4
// speedup vs baseline: 2.5162x; 1.1891x over previous
#include <cuda_runtime.h>
#include <math.h>

#define NTOK 1024
#define CQ   768
#define CZ   128
#define NH   16
#define HD   48

// ---------------- scratch (static device memory) ----------------
__device__ float g_an  [NTOK * CQ];
__device__ float g_q   [NTOK * CQ];
__device__ float g_k   [NTOK * CQ];
__device__ float g_v   [NTOK * CQ];
__device__ float g_gate[NTOK * CQ];
__device__ float g_og  [NTOK * CQ];
__device__ float g_sc  [(size_t)NTOK * NH * NTOK];   // pair+mask bias, layout [i][h][j]
__device__ float g_wp  [CZ * NH];
__device__ float g_wpT [NH * 132];                   // tf32(gz*wz) transposed [h][c]
__device__ float g_Wh  [NH];
__device__ float g_ch  [NH];

// ---------------- tf32 helpers ----------------
__device__ __forceinline__ unsigned f2tf(float x) {
    unsigned u; asm("cvt.rna.tf32.f32 %0, %1;" : "=r"(u) : "f"(x)); return u;
}
__device__ __forceinline__ float tf32f(float x) { return __uint_as_float(f2tf(x)); }
__device__ __forceinline__ unsigned su(float x) { return __float_as_uint(x); }

#define MMA_TF32(c, a, b0_, b1_)                                              \
    asm volatile("mma.sync.aligned.m16n8k8.row.col.f32.tf32.tf32.f32 "        \
                 "{%0,%1,%2,%3}, {%4,%5,%6,%7}, {%8,%9}, {%0,%1,%2,%3};"      \
                 : "+f"(c[0]), "+f"(c[1]), "+f"(c[2]), "+f"(c[3])             \
                 : "r"(a[0]), "r"(a[1]), "r"(a[2]), "r"(a[3]),                \
                   "r"(b0_), "r"(b1_));

// ---------------- LayerNorm of a ----------------
__global__ void __launch_bounds__(256) ln_a_kernel(const float* __restrict__ a,
                                                   const float* __restrict__ gw,
                                                   const float* __restrict__ bw) {
    int row = blockIdx.x;
    int tid = threadIdx.x;
    const float* x = a + (size_t)row * CQ;
    __shared__ float red[256];

    float xv[3];
    float s = 0.f;
#pragma unroll
    for (int k = 0; k < 3; k++) { xv[k] = x[tid + k * 256]; s += xv[k]; }
    red[tid] = s; __syncthreads();
    for (int st = 128; st > 0; st >>= 1) { if (tid < st) red[tid] += red[tid + st]; __syncthreads(); }
    float mu = red[0] * (1.f / CQ);
    __syncthreads();

    float s2 = 0.f;
#pragma unroll
    for (int k = 0; k < 3; k++) { float d = xv[k] - mu; s2 += d * d; }
    red[tid] = s2; __syncthreads();
    for (int st = 128; st > 0; st >>= 1) { if (tid < st) red[tid] += red[tid + st]; __syncthreads(); }
    float rs = rsqrtf(red[0] * (1.f / CQ) + 1e-5f);

#pragma unroll
    for (int k = 0; k < 3; k++) {
        int i = tid + k * 256;
        g_an[(size_t)row * CQ + i] = (xv[k] - mu) * rs * gw[i] + bw[i];
    }
}

// ---------------- pair-bias precompute ----------------
__global__ void prep_kernel(const float* __restrict__ gz,
                            const float* __restrict__ bz,
                            const float* __restrict__ wz) {
    int tid = threadIdx.x;       // 128
    float gzc = gz[tid];
    for (int h = 0; h < NH; h++) {
        float w = gzc * wz[tid * NH + h];
        g_wp[tid * NH + h] = w;
        g_wpT[h * 132 + tid] = tf32f(w);
    }
    __syncthreads();
    if (tid < NH) {
        float W = 0.f, C = 0.f;
        for (int c = 0; c < CZ; c++) {
            W += g_wp[c * NH + tid];
            C += bz[c] * wz[c * NH + tid];
        }
        g_Wh[tid] = W;
        g_ch[tid] = C;
    }
}

// ---------------- pair bias via tensor cores ----------------
// block: one i, 128 j rows. 256 threads = 8 warps x 16 rows. K=CZ=128, N=NH=16.
// dyn smem: zs[128][132] | sb[16][132] | mus[128] | rss[128]
__global__ void __launch_bounds__(256) pair_mma(const float* __restrict__ z,
                                                const float* __restrict__ mask) {
    extern __shared__ float psm[];
    float* zs  = psm;                     // 128*132
    float* wpt = zs + 128 * 132;          // 16*132
    float* sb  = wpt + 16 * 132;          // 16*132
    float* mus = sb + 16 * 132;           // 128
    float* rss = mus + 128;               // 128

    int i  = blockIdx.y;
    int j0 = blockIdx.x * 128;
    int tid = threadIdx.x, lane = tid & 31, w = tid >> 5;
    int g = lane >> 2, t = lane & 3;

    for (int e = tid; e < NH * 132; e += 256) wpt[e] = g_wpT[e];

    // load z rows (2 threads per row), fp32 stats + tf32 store
    int row = tid >> 1, c0 = (tid & 1) * 64;
    const float* zrow = z + ((size_t)i * NTOK + j0 + row) * CZ + c0;
    float s1 = 0.f, s2 = 0.f;
#pragma unroll
    for (int q = 0; q < 16; q++) {
        float4 v = *(const float4*)&zrow[q * 4];
        s1 += v.x + v.y + v.z + v.w;
        s2 += v.x * v.x + v.y * v.y + v.z * v.z + v.w * v.w;
        float4 hv = make_float4(tf32f(v.x), tf32f(v.y), tf32f(v.z), tf32f(v.w));
        *(float4*)&zs[row * 132 + c0 + q * 4] = hv;
    }
    s1 += __shfl_xor_sync(0xffffffffu, s1, 1);
    s2 += __shfl_xor_sync(0xffffffffu, s2, 1);
    float mu = s1 * (1.f / CZ);
    float var = s2 * (1.f / CZ) - mu * mu;
    float rs = rsqrtf(var + 1e-5f);
    if ((tid & 1) == 0) { mus[row] = mu; rss[row] = rs; }
    __syncthreads();

    // mma: rows wr..wr+15 x 16 heads, K=128
    int wr = w * 16;
    float c[2][4] = {};
#pragma unroll
    for (int ks = 0; ks < 16; ks++) {
        int kk = ks * 8;
        unsigned a[4];
        a[0] = su(zs[(wr + g) * 132 + kk + t]);
        a[1] = su(zs[(wr + g + 8) * 132 + kk + t]);
        a[2] = su(zs[(wr + g) * 132 + kk + t + 4]);
        a[3] = su(zs[(wr + g + 8) * 132 + kk + t + 4]);
#pragma unroll
        for (int nt = 0; nt < 2; nt++) {
            unsigned b0 = su(wpt[(nt * 8 + g) * 132 + kk + t]);
            unsigned b1 = su(wpt[(nt * 8 + g) * 132 + kk + t + 4]);
            MMA_TF32(c[nt], a, b0, b1);
        }
    }

    float muA = mus[wr + g], rsA = rss[wr + g];
    float muB = mus[wr + g + 8], rsB = rss[wr + g + 8];
#pragma unroll
    for (int nt = 0; nt < 2; nt++) {
#pragma unroll
        for (int cc = 0; cc < 2; cc++) {
            int h = nt * 8 + 2 * t + cc;
            float W = g_Wh[h], C0 = g_ch[h];
            sb[h * 132 + wr + g]     = rsA * (c[nt][cc]     - muA * W) + C0;
            sb[h * 132 + wr + g + 8] = rsB * (c[nt][cc + 2] - muB * W) + C0;
        }
    }
    __syncthreads();

    float mi = mask[i];
#pragma unroll
    for (int e = tid; e < NH * 128; e += 256) {
        int h = e >> 7, j = e & 127;
        float mb = 1.0e9f * (mi * mask[j0 + j] - 1.f);
        g_sc[((size_t)i * NH + h) * NTOK + j0 + j] = sb[h * 132 + j] + mb;
    }
}

// ================= 3xTF32 GEMM, pre-split hi/lo smem, BK=16, 128x64 tile =================
__device__ __forceinline__ void gemm_core(const float* __restrict__ A,
                                          const float* __restrict__ B,
                                          float c[2][4][4],
                                          float* sAh, float* sAl,
                                          float* sBh, float* sBl) {
    int tid  = threadIdx.x;
    int lane = tid & 31, w = tid >> 5;
    int wm = w & 3, wn = w >> 2;
    int g = lane >> 2, t = lane & 3;
    int m0 = blockIdx.y * 128, n0 = blockIdx.x * 64;
    int arow = tid >> 1, akb = (tid & 1) * 8;
    int bk = tid >> 4, bn = (tid & 15) * 4;

    for (int k0 = 0; k0 < CQ; k0 += 16) {
        __syncthreads();
        {
            float4 v0 = *(const float4*)&A[(size_t)(m0 + arow) * CQ + k0 + akb];
            float4 v1 = *(const float4*)&A[(size_t)(m0 + arow) * CQ + k0 + akb + 4];
            float xs[8] = {v0.x, v0.y, v0.z, v0.w, v1.x, v1.y, v1.z, v1.w};
#pragma unroll
            for (int q = 0; q < 8; q++) {
                float hi = tf32f(xs[q]);
                sAh[(akb + q) * 136 + arow] = hi;
                sAl[(akb + q) * 136 + arow] = tf32f(xs[q] - hi);
            }
        }
        {
            float4 v = *(const float4*)&B[(size_t)(k0 + bk) * CQ + n0 + bn];
            float4 hi = make_float4(tf32f(v.x), tf32f(v.y), tf32f(v.z), tf32f(v.w));
            float4 lo = make_float4(tf32f(v.x - hi.x), tf32f(v.y - hi.y),
                                    tf32f(v.z - hi.z), tf32f(v.w - hi.w));
            *(float4*)&sBh[bk * 72 + bn] = hi;
            *(float4*)&sBl[bk * 72 + bn] = lo;
        }
        __syncthreads();

#pragma unroll
        for (int ks = 0; ks < 2; ks++) {
            int kk = ks * 8;
            unsigned Ah[2][4], Al[2][4], Bh[4][2], Bl[4][2];
#pragma unroll
            for (int mt = 0; mt < 2; mt++) {
                int mb = wm * 32 + mt * 16 + g;
                Ah[mt][0] = su(sAh[(kk + t) * 136 + mb]);
                Ah[mt][1] = su(sAh[(kk + t) * 136 + mb + 8]);
                Ah[mt][2] = su(sAh[(kk + t + 4) * 136 + mb]);
                Ah[mt][3] = su(sAh[(kk + t + 4) * 136 + mb + 8]);
                Al[mt][0] = su(sAl[(kk + t) * 136 + mb]);
                Al[mt][1] = su(sAl[(kk + t) * 136 + mb + 8]);
                Al[mt][2] = su(sAl[(kk + t + 4) * 136 + mb]);
                Al[mt][3] = su(sAl[(kk + t + 4) * 136 + mb + 8]);
            }
#pragma unroll
            for (int nt = 0; nt < 4; nt++) {
                int nb = wn * 32 + nt * 8 + g;
                Bh[nt][0] = su(sBh[(kk + t) * 72 + nb]);
                Bh[nt][1] = su(sBh[(kk + t + 4) * 72 + nb]);
                Bl[nt][0] = su(sBl[(kk + t) * 72 + nb]);
                Bl[nt][1] = su(sBl[(kk + t + 4) * 72 + nb]);
            }
#pragma unroll
            for (int mt = 0; mt < 2; mt++)
#pragma unroll
                for (int nt = 0; nt < 4; nt++) {
                    MMA_TF32(c[mt][nt], Ah[mt], Bh[nt][0], Bh[nt][1]);
                    MMA_TF32(c[mt][nt], Ah[mt], Bl[nt][0], Bl[nt][1]);
                    MMA_TF32(c[mt][nt], Al[mt], Bh[nt][0], Bh[nt][1]);
                }
        }
    }
}

#define GEMM_SMEM                                                             \
    __shared__ float sAh[16 * 136], sAl[16 * 136];                            \
    __shared__ float sBh[16 * 72],  sBl[16 * 72];

// fused Q/K/V/Gate projections
__global__ void __launch_bounds__(256) qkvg_mma(const float* __restrict__ A,
                                                const float* __restrict__ wq,
                                                const float* __restrict__ wk,
                                                const float* __restrict__ wv,
                                                const float* __restrict__ wg,
                                                const float* __restrict__ bg,
                                                float qscale) {
    GEMM_SMEM
    int zi = blockIdx.z;
    const float* B = (zi == 0) ? wq : (zi == 1) ? wk : (zi == 2) ? wv : wg;
    float* O = (zi == 0) ? g_q : (zi == 1) ? g_k : (zi == 2) ? g_v : g_gate;

    float c[2][4][4] = {};
    gemm_core(A, B, c, sAh, sAl, sBh, sBl);

    int lane = threadIdx.x & 31, w = threadIdx.x >> 5;
    int wm = w & 3, wn = w >> 2;
    int g = lane >> 2, t = lane & 3;
    int m0 = blockIdx.y * 128, n0 = blockIdx.x * 64;
#pragma unroll
    for (int mt = 0; mt < 2; mt++) {
        int r0 = m0 + wm * 32 + mt * 16 + g;
#pragma unroll
        for (int nt = 0; nt < 4; nt++) {
            int col = n0 + wn * 32 + nt * 8 + 2 * t;
            float v0 = c[mt][nt][0], v1 = c[mt][nt][1];
            float v2 = c[mt][nt][2], v3 = c[mt][nt][3];
            if (zi == 0) { v0 *= qscale; v1 *= qscale; v2 *= qscale; v3 *= qscale; }
            if (zi == 3) {
                float2 bb = *(const float2*)&bg[col];
                v0 = 1.f / (1.f + __expf(-(v0 + bb.x)));
                v1 = 1.f / (1.f + __expf(-(v1 + bb.y)));
                v2 = 1.f / (1.f + __expf(-(v2 + bb.x)));
                v3 = 1.f / (1.f + __expf(-(v3 + bb.y)));
            }
            *(float2*)&O[(size_t)r0 * CQ + col]       = make_float2(v0, v1);
            *(float2*)&O[(size_t)(r0 + 8) * CQ + col] = make_float2(v2, v3);
        }
    }
}

// out projection
__global__ void __launch_bounds__(256) out_mma(const float* __restrict__ A,
                                               const float* __restrict__ B,
                                               float* __restrict__ C,
                                               const float* __restrict__ bias) {
    GEMM_SMEM
    float c[2][4][4] = {};
    gemm_core(A, B, c, sAh, sAl, sBh, sBl);

    int lane = threadIdx.x & 31, w = threadIdx.x >> 5;
    int wm = w & 3, wn = w >> 2;
    int g = lane >> 2, t = lane & 3;
    int m0 = blockIdx.y * 128, n0 = blockIdx.x * 64;
#pragma unroll
    for (int mt = 0; mt < 2; mt++) {
        int r0 = m0 + wm * 32 + mt * 16 + g;
#pragma unroll
        for (int nt = 0; nt < 4; nt++) {
            int col = n0 + wn * 32 + nt * 8 + 2 * t;
            float2 bb = *(const float2*)&bias[col];
            *(float2*)&C[(size_t)r0 * CQ + col] =
                make_float2(c[mt][nt][0] + bb.x, c[mt][nt][1] + bb.y);
            *(float2*)&C[(size_t)(r0 + 8) * CQ + col] =
                make_float2(c[mt][nt][2] + bb.x, c[mt][nt][3] + bb.y);
        }
    }
}

// ================= flash attention on mma: 64 rows x 1 head per block =================
__global__ void __launch_bounds__(128) flash_mma() {
    extern __shared__ float fsm[];
    float* Ks = fsm;                      // 64*68
    float* Vs = fsm + 4352;               // 64*72
    float* Ps = fsm + 4352 + 4608;        // 4*16*68

    int h  = blockIdx.y;
    int i0 = blockIdx.x * 64;
    int tid = threadIdx.x, w = tid >> 5, lane = tid & 31;
    int g = lane >> 2, t = lane & 3;
    float* Pw = Ps + w * (16 * 68);
    int irow = i0 + w * 16 + g;

    unsigned aq[6][4];
    {
        const float* q0 = g_q + (size_t)irow * CQ + h * HD;
        const float* q8 = q0 + 8 * CQ;
#pragma unroll
        for (int ks = 0; ks < 6; ks++) {
            aq[ks][0] = f2tf(q0[ks * 8 + t]);
            aq[ks][1] = f2tf(q8[ks * 8 + t]);
            aq[ks][2] = f2tf(q0[ks * 8 + t + 4]);
            aq[ks][3] = f2tf(q8[ks * 8 + t + 4]);
        }
    }

    float o[6][4] = {};
    float mrunA = -1e30f, mrunB = -1e30f, lA = 0.f, lB = 0.f;

    for (int jt = 0; jt < 16; jt++) {
        int j0 = jt * 64;
        __syncthreads();
        for (int e = tid; e < 768; e += 128) {
            int r = e / 12, cc = (e % 12) * 4;
            float4 kv = *(const float4*)&g_k[(size_t)(j0 + r) * CQ + h * HD + cc];
            Ks[r * 68 + cc + 0] = tf32f(kv.x); Ks[r * 68 + cc + 1] = tf32f(kv.y);
            Ks[r * 68 + cc + 2] = tf32f(kv.z); Ks[r * 68 + cc + 3] = tf32f(kv.w);
            float4 vv = *(const float4*)&g_v[(size_t)(j0 + r) * CQ + h * HD + cc];
            Vs[r * 72 + cc + 0] = tf32f(vv.x); Vs[r * 72 + cc + 1] = tf32f(vv.y);
            Vs[r * 72 + cc + 2] = tf32f(vv.z); Vs[r * 72 + cc + 3] = tf32f(vv.w);
        }
        for (int e = lane; e < 256; e += 32) {
            int r = e >> 4, c4 = (e & 15) * 4;
            *(float4*)&Pw[r * 68 + c4] =
                *(const float4*)&g_sc[((size_t)(i0 + w * 16 + r) * NH + h) * NTOK + j0 + c4];
        }
        __syncthreads();

        float s[8][4];
#pragma unroll
        for (int nt = 0; nt < 8; nt++) {
            float2 bA = *(const float2*)&Pw[g * 68 + nt * 8 + 2 * t];
            float2 bB = *(const float2*)&Pw[(g + 8) * 68 + nt * 8 + 2 * t];
            s[nt][0] = bA.x; s[nt][1] = bA.y; s[nt][2] = bB.x; s[nt][3] = bB.y;
        }
#pragma unroll
        for (int ks = 0; ks < 6; ks++) {
#pragma unroll
            for (int nt = 0; nt < 8; nt++) {
                unsigned b0 = su(Ks[(nt * 8 + g) * 68 + ks * 8 + t]);
                unsigned b1 = su(Ks[(nt * 8 + g) * 68 + ks * 8 + t + 4]);
                MMA_TF32(s[nt], aq[ks], b0, b1);
            }
        }

        float mA = -1e30f, mB = -1e30f;
#pragma unroll
        for (int nt = 0; nt < 8; nt++) {
            mA = fmaxf(mA, fmaxf(s[nt][0], s[nt][1]));
            mB = fmaxf(mB, fmaxf(s[nt][2], s[nt][3]));
        }
#pragma unroll
        for (int oo = 1; oo <= 2; oo <<= 1) {
            mA = fmaxf(mA, __shfl_xor_sync(0xffffffffu, mA, oo));
            mB = fmaxf(mB, __shfl_xor_sync(0xffffffffu, mB, oo));
        }
        float mnA = fmaxf(mrunA, mA), mnB = fmaxf(mrunB, mB);
        float alA = __expf(mrunA - mnA), alB = __expf(mrunB - mnB);
        mrunA = mnA; mrunB = mnB;

        float sumA = 0.f, sumB = 0.f;
#pragma unroll
        for (int nt = 0; nt < 8; nt++) {
            s[nt][0] = __expf(s[nt][0] - mnA); s[nt][1] = __expf(s[nt][1] - mnA);
            s[nt][2] = __expf(s[nt][2] - mnB); s[nt][3] = __expf(s[nt][3] - mnB);
            sumA += s[nt][0] + s[nt][1];
            sumB += s[nt][2] + s[nt][3];
        }
#pragma unroll
        for (int oo = 1; oo <= 2; oo <<= 1) {
            sumA += __shfl_xor_sync(0xffffffffu, sumA, oo);
            sumB += __shfl_xor_sync(0xffffffffu, sumB, oo);
        }
        lA = lA * alA + sumA;
        lB = lB * alB + sumB;
#pragma unroll
        for (int nd = 0; nd < 6; nd++) {
            o[nd][0] *= alA; o[nd][1] *= alA;
            o[nd][2] *= alB; o[nd][3] *= alB;
        }

#pragma unroll
        for (int nt = 0; nt < 8; nt++) {
            *(float2*)&Pw[g * 68 + nt * 8 + 2 * t]       = make_float2(tf32f(s[nt][0]), tf32f(s[nt][1]));
            *(float2*)&Pw[(g + 8) * 68 + nt * 8 + 2 * t] = make_float2(tf32f(s[nt][2]), tf32f(s[nt][3]));
        }
        __syncwarp();

#pragma unroll
        for (int ks = 0; ks < 8; ks++) {
            unsigned pa[4];
            pa[0] = su(Pw[g * 68 + ks * 8 + t]);
            pa[1] = su(Pw[(g + 8) * 68 + ks * 8 + t]);
            pa[2] = su(Pw[g * 68 + ks * 8 + t + 4]);
            pa[3] = su(Pw[(g + 8) * 68 + ks * 8 + t + 4]);
#pragma unroll
            for (int nd = 0; nd < 6; nd++) {
                unsigned b0 = su(Vs[(ks * 8 + t) * 72 + nd * 8 + g]);
                unsigned b1 = su(Vs[(ks * 8 + t + 4) * 72 + nd * 8 + g]);
                MMA_TF32(o[nd], pa, b0, b1);
            }
        }
    }

    float iA = 1.f / lA, iB = 1.f / lB;
#pragma unroll
    for (int nd = 0; nd < 6; nd++) {
        int col = h * HD + nd * 8 + 2 * t;
        size_t iAx = (size_t)irow * CQ + col;
        size_t iBx = (size_t)(irow + 8) * CQ + col;
        float2 ga = *(const float2*)&g_gate[iAx];
        float2 gb = *(const float2*)&g_gate[iBx];
        *(float2*)&g_og[iAx] = make_float2(o[nd][0] * iA * ga.x, o[nd][1] * iA * ga.y);
        *(float2*)&g_og[iBx] = make_float2(o[nd][2] * iB * gb.x, o[nd][3] * iB * gb.y);
    }
}

// ------------------------------- launch -------------------------------
#define PB_SMEM ((128 * 132 + 16 * 132 + 16 * 132 + 256) * 4)

extern "C" void kernel_launch(void* const* d_in, const int* in_sizes, int n_in,
                              void* d_out, int out_size) {
    const float* a    = (const float*)d_in[0];
    const float* z    = (const float*)d_in[1];
    const float* mask = (const float*)d_in[2];
    const float* ga   = (const float*)d_in[3];
    const float* ba   = (const float*)d_in[4];
    const float* gz   = (const float*)d_in[5];
    const float* bz   = (const float*)d_in[6];
    const float* wz   = (const float*)d_in[7];
    const float* wq   = (const float*)d_in[8];
    const float* wk   = (const float*)d_in[9];
    const float* wv   = (const float*)d_in[10];
    const float* wg   = (const float*)d_in[11];
    const float* bg   = (const float*)d_in[12];
    const float* wo   = (const float*)d_in[13];
    const float* bo   = (const float*)d_in[14];
    float* out = (float*)d_out;

    float *p_an, *p_og;
    cudaGetSymbolAddress((void**)&p_an, g_an);
    cudaGetSymbolAddress((void**)&p_og, g_og);

    static int smem_set = 0;
    if (!smem_set) {
        cudaFuncSetAttribute(flash_mma, cudaFuncAttributeMaxDynamicSharedMemorySize, 53248);
        cudaFuncSetAttribute(pair_mma,  cudaFuncAttributeMaxDynamicSharedMemorySize, PB_SMEM);
        smem_set = 1;
    }

    ln_a_kernel<<<NTOK, 256>>>(a, ga, ba);
    prep_kernel<<<1, 128>>>(gz, bz, wz);
    pair_mma<<<dim3(NTOK / 128, NTOK), 256, PB_SMEM>>>(z, mask);

    float qscale = 1.0f / sqrtf((float)HD);
    qkvg_mma<<<dim3(CQ / 64, NTOK / 128, 4), 256>>>(p_an, wq, wk, wv, wg, bg, qscale);

    flash_mma<<<dim3(NTOK / 64, NH), 128, 53248>>>();

    out_mma<<<dim3(CQ / 64, NTOK / 128), 256>>>(p_og, wo, out, bo);
}